// round 1
// baseline (speedup 1.0000x reference)
#include <cuda_runtime.h>
#include <cuda_bf16.h>

// ---------------------------------------------------------------------------
// RSSM: B=1024, T=128, OBS=64, ACT=8, D=256, S=32, H=256
// out[b][t][416] = [h(256) | z(32) | pm(32) | ps(32) | qm(32) | qs(32)]
//
// Phase 1 (prep):  transpose/fuse weights into [K][N] layouts for f32x2 GEMMs
// Phase 2 (emb):   parallel over (b,t): q1emb = elu(elu(obs@We1)@We2) @ Wq1_emb + b_q1
// Phase 3 (seq):   128 CTAs x 8 batch rows, loop t=0..127, full step per CTA
// ---------------------------------------------------------------------------

typedef unsigned long long u64;

#define Bsz 1024
#define Tn  128
#define Dd  256
#define Ss  32
#define Hh  256

// ---- packed f32x2 helpers -------------------------------------------------
__device__ __forceinline__ void fma2(u64 &d, u64 a, u64 b) {
    asm("fma.rn.f32x2 %0, %1, %2, %0;" : "+l"(d) : "l"(a), "l"(b));
}
__device__ __forceinline__ u64 pk2(float x) {
    u64 r; unsigned xi = __float_as_uint(x);
    asm("mov.b64 %0, {%1, %2};" : "=l"(r) : "r"(xi), "r"(xi));
    return r;
}
__device__ __forceinline__ float2 upk(u64 v) {
    unsigned lo, hi;
    asm("mov.b64 {%0, %1}, %2;" : "=r"(lo), "=r"(hi) : "l"(v));
    return make_float2(__uint_as_float(lo), __uint_as_float(hi));
}
__device__ __forceinline__ float eluf(float x)  { return x > 0.f ? x : expm1f(x); }
__device__ __forceinline__ float sigf(float x)  { return 1.f / (1.f + expf(-x)); }
__device__ __forceinline__ float clipf(float x) { return fminf(fmaxf(x, -7.f), 5.f); }

// ---- device scratch (static, no allocations) ------------------------------
__device__ float g_Wbig [256 * 1280];   // [k][n] n: 0-255 W_p1 | 256-511 W_q1(h) | 512-1279 W_hh
__device__ float g_Wih  [40 * 768];     // [k][n] k: 0-31 z part, 32-39 act part
__device__ float g_Wp2  [256 * 64];     // [k][j]
__device__ float g_Wq2  [256 * 64];     // [k][j]
__device__ float g_We1  [64 * 256];     // [k][n]
__device__ float g_We2  [256 * 256];    // [k][n]
__device__ float g_Wq1e [256 * 256];    // [k][n] = W_q1[n][256+k]
__device__ float g_q1emb[(long)Bsz * Tn * 256];  // 134 MB: emb @ Wq1_emb + b_q1

// ---------------------------------------------------------------------------
// prep: build transposed/fused weight layouts
// ---------------------------------------------------------------------------
__global__ void prep_kernel(const float* __restrict__ Wp1, const float* __restrict__ Wq1,
                            const float* __restrict__ Whh, const float* __restrict__ Wih,
                            const float* __restrict__ Wp2, const float* __restrict__ Wq2,
                            const float* __restrict__ We1, const float* __restrict__ We2)
{
    int tid = blockIdx.x * blockDim.x + threadIdx.x;
    int nt  = gridDim.x * blockDim.x;
    for (int i = tid; i < 256 * 1280; i += nt) {
        int k = i / 1280, n = i % 1280;
        float v;
        if (n < 256)      v = Wp1[n * 256 + k];
        else if (n < 512) v = Wq1[(n - 256) * 512 + k];
        else              v = Whh[(n - 512) * 256 + k];
        g_Wbig[i] = v;
    }
    for (int i = tid; i < 40 * 768; i += nt) {
        int k = i / 768, n = i % 768;
        g_Wih[i] = Wih[n * 40 + k];
    }
    for (int i = tid; i < 256 * 64; i += nt) {
        int k = i / 64, j = i % 64;
        g_Wp2[i] = Wp2[j * 256 + k];
        g_Wq2[i] = Wq2[j * 256 + k];
    }
    for (int i = tid; i < 64 * 256; i += nt) {
        int k = i / 256, n = i % 256;
        g_We1[i] = We1[n * 64 + k];
    }
    for (int i = tid; i < 256 * 256; i += nt) {
        int k = i / 256, n = i % 256;
        g_We2[i]  = We2[n * 256 + k];
        g_Wq1e[i] = Wq1[n * 512 + 256 + k];
    }
}

// ---------------------------------------------------------------------------
// emb: per (b,t) row: e1 = elu(obs@We1+b1); e2 = elu(e1@We2+b2);
//      q1emb = e2@Wq1e + b_q1   (elu of posterior applied later, after h-part)
// 64 rows per CTA, 256 threads: 2 groups of 128 threads x 32 rows.
// thread owns column-pair n = 2*(tid&127); f32x2 accumulate.
// ---------------------------------------------------------------------------
#define EROWS 64
#define EMB_SMEM ((EROWS*64 + 2*EROWS*256) * 4)

__global__ void __launch_bounds__(256, 1) emb_kernel(
    const float* __restrict__ obs, const float* __restrict__ be1,
    const float* __restrict__ be2, const float* __restrict__ bq1)
{
    extern __shared__ float sm[];
    float* obs_s = sm;                  // 64*64
    float* e1_s  = sm + EROWS * 64;     // 64*256
    float* e2_s  = e1_s + EROWS * 256;  // 64*256

    int tid  = threadIdx.x;
    int row0 = blockIdx.x * EROWS;

    for (int i = tid; i < EROWS * 64; i += 256) obs_s[i] = obs[(long)row0 * 64 + i];
    __syncthreads();

    int g  = tid >> 7;      // 0..1
    int p  = tid & 127;     // column pair -> cols 2p, 2p+1
    int r0 = g * 32;
    int n  = 2 * p;
    u64 acc[32];

    // stage 1: K=64
    #pragma unroll
    for (int r = 0; r < 32; r++) acc[r] = 0ull;
    {
        const u64* W = (const u64*)g_We1;
        #pragma unroll 4
        for (int k = 0; k < 64; k++) {
            u64 w = W[k * 128 + p];
            #pragma unroll
            for (int r = 0; r < 32; r++)
                fma2(acc[r], pk2(obs_s[(r0 + r) * 64 + k]), w);
        }
        float bx = be1[n], by = be1[n + 1];
        #pragma unroll
        for (int r = 0; r < 32; r++) {
            float2 v = upk(acc[r]);
            v.x = eluf(v.x + bx); v.y = eluf(v.y + by);
            *(float2*)&e1_s[(r0 + r) * 256 + n] = v;
        }
    }
    __syncthreads();

    // stage 2: K=256
    #pragma unroll
    for (int r = 0; r < 32; r++) acc[r] = 0ull;
    {
        const u64* W = (const u64*)g_We2;
        #pragma unroll 4
        for (int k = 0; k < 256; k++) {
            u64 w = W[k * 128 + p];
            #pragma unroll
            for (int r = 0; r < 32; r++)
                fma2(acc[r], pk2(e1_s[(r0 + r) * 256 + k]), w);
        }
        float bx = be2[n], by = be2[n + 1];
        #pragma unroll
        for (int r = 0; r < 32; r++) {
            float2 v = upk(acc[r]);
            v.x = eluf(v.x + bx); v.y = eluf(v.y + by);
            *(float2*)&e2_s[(r0 + r) * 256 + n] = v;
        }
    }
    __syncthreads();

    // stage 3: K=256 -> global q1emb (+ b_q1, no elu)
    #pragma unroll
    for (int r = 0; r < 32; r++) acc[r] = 0ull;
    {
        const u64* W = (const u64*)g_Wq1e;
        #pragma unroll 4
        for (int k = 0; k < 256; k++) {
            u64 w = W[k * 128 + p];
            #pragma unroll
            for (int r = 0; r < 32; r++)
                fma2(acc[r], pk2(e2_s[(r0 + r) * 256 + k]), w);
        }
        float bx = bq1[n], by = bq1[n + 1];
        #pragma unroll
        for (int r = 0; r < 32; r++) {
            float2 v = upk(acc[r]);
            v.x += bx; v.y += by;
            *(float2*)&g_q1emb[(long)(row0 + r0 + r) * 256 + n] = v;
        }
    }
}

// ---------------------------------------------------------------------------
// seq: 128 CTAs x 8 batch rows, persistent over t=0..127.
//  stage 1: G1[8][1280] = h @ [W_p1 | W_q1h | W_hh]   (+bias/q1emb, elu)
//  stage 2: pstats/qstats [8][128]                    (+bias, exp-clip)
//  stage 2.5: z, x=[z,a], write out row (old h)
//  stage 3: gi[8][768] = x @ W_ih + b_ih
//  stage 4: GRU gates -> h_new
// ---------------------------------------------------------------------------
#define SQ_THREADS 320
#define SEQ_SMEM ((8*256 + 8*1280 + 8*768 + 8*128 + 8*40) * 4)

__global__ void __launch_bounds__(SQ_THREADS, 1) seq_kernel(
    const float* __restrict__ act,  const float* __restrict__ noise,
    const float* __restrict__ b_p1, const float* __restrict__ b_hh,
    const float* __restrict__ b_p2, const float* __restrict__ b_q2,
    const float* __restrict__ b_ih, float* __restrict__ out)
{
    extern __shared__ float sm[];
    float* h_s  = sm;               // 8*256
    float* G1_s = h_s  + 8 * 256;   // 8*1280
    float* gi_s = G1_s + 8 * 1280;  // 8*768
    float* pq_s = gi_s + 8 * 768;   // 8*128 : pm|ps|qm|qs
    float* x_s  = pq_s + 8 * 128;   // 8*40  : [z(32) | a(8)]

    int tid = threadIdx.x;
    int b0  = blockIdx.x * 8;

    for (int i = tid; i < 8 * 256; i += SQ_THREADS) h_s[i] = 0.f;
    __syncthreads();

    const u64* Wb  = (const u64*)g_Wbig;   // [256][640]
    const u64* Wi  = (const u64*)g_Wih;    // [40][384]
    const u64* Wp2 = (const u64*)g_Wp2;    // [256][32]
    const u64* Wq2 = (const u64*)g_Wq2;    // [256][32]

    for (int t = 0; t < Tn; t++) {
        // -------- stage 1: big GEMM from h --------
        {
            u64 acc[8][2];
            #pragma unroll
            for (int r = 0; r < 8; r++) { acc[r][0] = 0ull; acc[r][1] = 0ull; }
            #pragma unroll 4
            for (int k = 0; k < 256; k++) {
                u64 w0 = Wb[k * 640 + tid];
                u64 w1 = Wb[k * 640 + 320 + tid];
                #pragma unroll
                for (int r = 0; r < 8; r++) {
                    u64 hp = pk2(h_s[r * 256 + k]);
                    fma2(acc[r][0], hp, w0);
                    fma2(acc[r][1], hp, w1);
                }
            }
            #pragma unroll
            for (int j = 0; j < 2; j++) {
                int p = tid + j * 320;
                int n = 2 * p;
                if (n < 256) {                     // prior hidden: elu(. + b_p1)
                    float bx = b_p1[n], by = b_p1[n + 1];
                    #pragma unroll
                    for (int r = 0; r < 8; r++) {
                        float2 v = upk(acc[r][j]);
                        v.x = eluf(v.x + bx); v.y = eluf(v.y + by);
                        *(float2*)&G1_s[r * 1280 + n] = v;
                    }
                } else if (n < 512) {              // post hidden: elu(. + q1emb) (b_q1 folded)
                    #pragma unroll
                    for (int r = 0; r < 8; r++) {
                        float2 q = *(const float2*)&g_q1emb[((long)(b0 + r) * Tn + t) * 256 + (n - 256)];
                        float2 v = upk(acc[r][j]);
                        v.x = eluf(v.x + q.x); v.y = eluf(v.y + q.y);
                        *(float2*)&G1_s[r * 1280 + n] = v;
                    }
                } else {                           // gh: . + b_hh
                    float bx = b_hh[n - 512], by = b_hh[n - 511];
                    #pragma unroll
                    for (int r = 0; r < 8; r++) {
                        float2 v = upk(acc[r][j]);
                        v.x += bx; v.y += by;
                        *(float2*)&G1_s[r * 1280 + n] = v;
                    }
                }
            }
        }
        __syncthreads();

        // -------- stage 2: stats GEMMs (threads 0..255) --------
        if (tid < 256) {
            int r = tid >> 5, c = tid & 31;
            u64 aP = 0ull, aQ = 0ull;
            #pragma unroll 4
            for (int k = 0; k < 256; k++) {
                u64 ph = pk2(G1_s[r * 1280 + k]);
                u64 qh = pk2(G1_s[r * 1280 + 256 + k]);
                fma2(aP, ph, Wp2[k * 32 + c]);
                fma2(aQ, qh, Wq2[k * 32 + c]);
            }
            int jn = 2 * c;
            float2 vP = upk(aP), vQ = upk(aQ);
            vP.x += b_p2[jn]; vP.y += b_p2[jn + 1];
            vQ.x += b_q2[jn]; vQ.y += b_q2[jn + 1];
            if (c >= 16) {                         // logstd half -> std
                vP.x = expf(clipf(vP.x)); vP.y = expf(clipf(vP.y));
                vQ.x = expf(clipf(vQ.x)); vQ.y = expf(clipf(vQ.y));
            }
            *(float2*)&pq_s[r * 128 + jn]      = vP;  // pm(0:32) ps(32:64)
            *(float2*)&pq_s[r * 128 + 64 + jn] = vQ;  // qm(64:96) qs(96:128)
        }
        __syncthreads();

        // -------- stage 2.5: z, x=[z,a], write outputs --------
        for (int i = tid; i < 8 * 32; i += SQ_THREADS) {
            int r = i >> 5, s = i & 31;
            float qm = pq_s[r * 128 + 64 + s];
            float qs = pq_s[r * 128 + 96 + s];
            float ep = noise[((long)t * Bsz + b0 + r) * 32 + s];
            float z  = qm + qs * ep;
            x_s[r * 40 + s] = z;
            out[((long)(b0 + r) * Tn + t) * 416 + 256 + s] = z;
        }
        for (int i = tid; i < 8 * 8; i += SQ_THREADS) {
            int r = i >> 3, j = i & 7;
            x_s[r * 40 + 32 + j] = act[((long)(b0 + r) * Tn + t) * 8 + j];
        }
        for (int i = tid; i < 8 * 256; i += SQ_THREADS) {
            int r = i >> 8, d = i & 255;
            out[((long)(b0 + r) * Tn + t) * 416 + d] = h_s[i];          // old h
        }
        for (int i = tid; i < 8 * 128; i += SQ_THREADS) {
            int r = i >> 7, c = i & 127;
            out[((long)(b0 + r) * Tn + t) * 416 + 288 + c] = pq_s[i];   // pm ps qm qs
        }
        __syncthreads();

        // -------- stage 3: gi = x @ W_ih + b_ih --------
        #pragma unroll
        for (int pp = 0; pp < 2; pp++) {
            int p = tid + pp * 320;
            if (p < 384) {
                u64 a3[8];
                #pragma unroll
                for (int r = 0; r < 8; r++) a3[r] = 0ull;
                #pragma unroll
                for (int k = 0; k < 40; k++) {
                    u64 w = Wi[k * 384 + p];
                    #pragma unroll
                    for (int r = 0; r < 8; r++)
                        fma2(a3[r], pk2(x_s[r * 40 + k]), w);
                }
                int n = 2 * p;
                float bx = b_ih[n], by = b_ih[n + 1];
                #pragma unroll
                for (int r = 0; r < 8; r++) {
                    float2 v = upk(a3[r]);
                    v.x += bx; v.y += by;
                    *(float2*)&gi_s[r * 768 + n] = v;
                }
            }
        }
        __syncthreads();

        // -------- stage 4: GRU gates --------
        for (int i = tid; i < 8 * 256; i += SQ_THREADS) {
            int r = i >> 8, d = i & 255;
            float gir = gi_s[r * 768 + d];
            float giz = gi_s[r * 768 + 256 + d];
            float gin = gi_s[r * 768 + 512 + d];
            float ghr = G1_s[r * 1280 + 512 + d];
            float ghz = G1_s[r * 1280 + 768 + d];
            float ghn = G1_s[r * 1280 + 1024 + d];
            float rg = sigf(gir + ghr);
            float ug = sigf(giz + ghz);
            float ng = tanhf(gin + rg * ghn);
            float ho = h_s[i];
            h_s[i] = (1.f - ug) * ng + ug * ho;
        }
        __syncthreads();
    }
}

// ---------------------------------------------------------------------------
extern "C" void kernel_launch(void* const* d_in, const int* in_sizes, int n_in,
                              void* d_out, int out_size)
{
    const float* obs  = (const float*)d_in[0];
    const float* act  = (const float*)d_in[1];
    const float* noi  = (const float*)d_in[2];
    const float* We1  = (const float*)d_in[3];
    const float* be1  = (const float*)d_in[4];
    const float* We2  = (const float*)d_in[5];
    const float* be2  = (const float*)d_in[6];
    const float* Wih  = (const float*)d_in[7];
    const float* Whh  = (const float*)d_in[8];
    const float* bih  = (const float*)d_in[9];
    const float* bhh  = (const float*)d_in[10];
    const float* Wp1  = (const float*)d_in[11];
    const float* bp1  = (const float*)d_in[12];
    const float* Wp2  = (const float*)d_in[13];
    const float* bp2  = (const float*)d_in[14];
    const float* Wq1  = (const float*)d_in[15];
    const float* bq1  = (const float*)d_in[16];
    const float* Wq2  = (const float*)d_in[17];
    const float* bq2  = (const float*)d_in[18];
    float* out = (float*)d_out;

    cudaFuncSetAttribute(emb_kernel, cudaFuncAttributeMaxDynamicSharedMemorySize, EMB_SMEM);
    cudaFuncSetAttribute(seq_kernel, cudaFuncAttributeMaxDynamicSharedMemorySize, SEQ_SMEM);

    prep_kernel<<<64, 256>>>(Wp1, Wq1, Whh, Wih, Wp2, Wq2, We1, We2);
    emb_kernel<<<(Bsz * Tn) / EROWS, 256, EMB_SMEM>>>(obs, be1, be2, bq1);
    seq_kernel<<<Bsz / 8, SQ_THREADS, SEQ_SMEM>>>(act, noi, bp1, bhh, bp2, bq2, bih, out);
}